// round 5
// baseline (speedup 1.0000x reference)
#include <cuda_runtime.h>
#include <cstdint>

#define ULL unsigned long long

// ---------- packed f32x2 helpers (sm_100+ PTX) ----------
__device__ __forceinline__ void fma2(ULL& d, ULL a, ULL b) {
    asm("fma.rn.f32x2 %0, %1, %2, %0;" : "+l"(d) : "l"(a), "l"(b));
}
__device__ __forceinline__ ULL mul2(ULL a, ULL b) {
    ULL d; asm("mul.rn.f32x2 %0, %1, %2;" : "=l"(d) : "l"(a), "l"(b)); return d;
}
__device__ __forceinline__ ULL pk(float lo, float hi) {
    ULL d; asm("mov.b64 %0, {%1, %2};" : "=l"(d) : "f"(lo), "f"(hi)); return d;
}
__device__ __forceinline__ float2 upk(ULL v) {
    float2 r; asm("mov.b64 {%0, %1}, %2;" : "=f"(r.x), "=f"(r.y) : "l"(v)); return r;
}

// ---------- static scratch ----------
__device__ float g_UP[4096 * 256];
__device__ float g_UH[4096 * 256];
__device__ float g_W1cP[256 * 358];
__device__ float g_W1cH[256 * 154];
__device__ float g_H1P[4096 * 358];
__device__ float g_H1H[4096 * 154];

struct EncArgs { const float* emb; const float* mask; const float* Ac; const float* Bc; float* U; int L; };
struct PreArgs { const float* A; const float* B; float* C; int N, K, nbx, nblocks; };
struct GemmArgs { const float* A; const float* B; const float* bias; float* C; int N, K, ldc; };

// =====================================================================
// Encoders (both branches via blockIdx.z).
// Block = 128 thr = 4 warps = 2 samples; warp w: sample w>>1, d-half w&1.
// Thread: 2 consecutive d, all 16 q as 8 q-pair f32x2 accumulators.
// Software-pipelined LDG (ping-pong groups of 4 rows).
// =====================================================================
__global__ __launch_bounds__(128, 6)
void encoders(EncArgs e0, EncArgs e1)
{
    const EncArgs e = blockIdx.z ? e1 : e0;
    const int L = e.L;
    extern __shared__ __align__(16) char smem[];
    float* acs  = (float*)smem;                       // L*16 raw Ac
    ULL*   mdup = (ULL*)(smem + (size_t)L * 64);      // [2][L] dup masks
    // phase-2 overlay
    float* Bcs = (float*)smem;                        // 2048 floats
    float* Vs  = (float*)(smem + 8192);               // 2 * 16 * 130

    const int tid  = threadIdx.x;
    const int w    = tid >> 5;
    const int lane = tid & 31;
    const int b0   = blockIdx.x * 2;
    const int s    = w >> 1;
    const int h    = w & 1;

    const ULL* xg = (const ULL*)(e.emb + (size_t)(b0 + s) * L * 128) + h * 32 + lane;

    // issue first LDG group before staging (overlap)
    ULL xb[4];
#pragma unroll
    for (int u = 0; u < 4; u++) xb[u] = xg[(size_t)u * 64];

    for (int i = tid; i < L * 16; i += 128) acs[i] = e.Ac[i];
    for (int i = tid; i < 2 * L; i += 128) {
        int ss = i / L, l = i - ss * L;
        float m = e.mask[(size_t)(b0 + ss) * L + l];
        mdup[i] = pk(m, m);
    }
    __syncthreads();

    const ULL* mp = mdup + s * L;
    const ulonglong2* acp = (const ulonglong2*)acs;   // [L][4]

    ULL V[8][2];
#pragma unroll
    for (int p = 0; p < 8; p++) { V[p][0] = 0ull; V[p][1] = 0ull; }

    auto proc = [&](int l, ULL xv) {
        ULL xm = mul2(xv, mp[l]);
        float2 f = upk(xm);
        ULL X0 = pk(f.x, f.x);
        ULL X1 = pk(f.y, f.y);
        ulonglong2 a01 = acp[l * 4 + 0];
        ulonglong2 a23 = acp[l * 4 + 1];
        ulonglong2 a45 = acp[l * 4 + 2];
        ulonglong2 a67 = acp[l * 4 + 3];
        fma2(V[0][0], a01.x, X0); fma2(V[0][1], a01.x, X1);
        fma2(V[1][0], a01.y, X0); fma2(V[1][1], a01.y, X1);
        fma2(V[2][0], a23.x, X0); fma2(V[2][1], a23.x, X1);
        fma2(V[3][0], a23.y, X0); fma2(V[3][1], a23.y, X1);
        fma2(V[4][0], a45.x, X0); fma2(V[4][1], a45.x, X1);
        fma2(V[5][0], a45.y, X0); fma2(V[5][1], a45.y, X1);
        fma2(V[6][0], a67.x, X0); fma2(V[6][1], a67.x, X1);
        fma2(V[7][0], a67.y, X0); fma2(V[7][1], a67.y, X1);
    };

    // ping-pong: load next group of 4 before processing current group
    for (int l0 = 0; l0 < L; l0 += 8) {
        ULL xn[4];
#pragma unroll
        for (int u = 0; u < 4; u++) xn[u] = xg[(size_t)(l0 + 4 + u) * 64];
#pragma unroll
        for (int u = 0; u < 4; u++) proc(l0 + u, xb[u]);
        if (l0 + 8 < L) {
#pragma unroll
            for (int u = 0; u < 4; u++) xb[u] = xg[(size_t)(l0 + 8 + u) * 64];
        }
#pragma unroll
        for (int u = 0; u < 4; u++) proc(l0 + 4 + u, xn[u]);
    }
    __syncthreads();   // acs/mdup dead

    // stage V: Vs[s][q][d], pitch 130
    const int d0 = h * 64 + lane * 2;
    {
        float* vb = Vs + s * 2080;
#pragma unroll
        for (int p = 0; p < 8; p++) {
            float2 v0 = upk(V[p][0]);   // d0   : {q=2p, q=2p+1}
            float2 v1 = upk(V[p][1]);   // d0+1 : {q=2p, q=2p+1}
            vb[(2 * p) * 130 + d0]         = v0.x;
            vb[(2 * p + 1) * 130 + d0]     = v0.y;
            vb[(2 * p) * 130 + d0 + 1]     = v1.x;
            vb[(2 * p + 1) * 130 + d0 + 1] = v1.y;
        }
    }
    for (int i = tid; i < 2048; i += 128) Bcs[i] = e.Bc[i];
    __syncthreads();

    // U = V @ Bc : warp covers 8 q x 16 r of its sample
    {
        const int q  = h * 8 + (lane >> 2);
        const int r0 = (lane & 3) * 4;
        ULL u0 = 0ull, u1 = 0ull;
        const float* vrow = Vs + s * 2080 + q * 130;
#pragma unroll 8
        for (int d = 0; d < 128; d++) {
            float v = vrow[d];
            ULL vv = pk(v, v);
            ulonglong2 b2 = *(const ulonglong2*)(Bcs + d * 16 + r0);
            fma2(u0, vv, b2.x);
            fma2(u1, vv, b2.y);
        }
        ULL* dst = (ULL*)(e.U + (size_t)(b0 + s) * 256 + q * 16 + r0);
        dst[0] = u0; dst[1] = u1;
    }
}

// =====================================================================
// Weight precombine (W1c = Hc @ W1), standalone kernel, 32x32 tiles
// =====================================================================
__global__ __launch_bounds__(128)
void precombine(PreArgs p0, PreArgs p1)
{
    const PreArgs p = blockIdx.z ? p1 : p0;
    if ((int)blockIdx.x >= p.nblocks) return;
    __shared__ float As[32 * 33];
    __shared__ float Bs[32 * 33];
    const int tid = threadIdx.x;
    const int tx = tid & 15, ty = tid >> 4;
    const int bn = (blockIdx.x % p.nbx) * 32;
    const int bm = (blockIdx.x / p.nbx) * 32;
    const int M = 256;

    float c[4][2];
#pragma unroll
    for (int i = 0; i < 4; i++) { c[i][0] = 0.f; c[i][1] = 0.f; }

    for (int k0 = 0; k0 < p.K; k0 += 32) {
#pragma unroll
        for (int i = 0; i < 8; i++) {
            int idx = tid + i * 128;
            int m = idx >> 5, k = idx & 31;
            int kg = k0 + k;
            As[k * 33 + m] = (kg < p.K && (bm + m) < M) ? p.A[(size_t)(bm + m) * p.K + kg] : 0.f;
            int kb = idx >> 5, nb = idx & 31;
            int kgb = k0 + kb, ng = bn + nb;
            Bs[kb * 33 + nb] = (kgb < p.K && ng < p.N) ? p.B[(size_t)kgb * p.N + ng] : 0.f;
        }
        __syncthreads();
#pragma unroll
        for (int kk = 0; kk < 32; kk++) {
            float b0 = Bs[kk * 33 + tx * 2], b1 = Bs[kk * 33 + tx * 2 + 1];
#pragma unroll
            for (int i = 0; i < 4; i++) {
                float a = As[kk * 33 + ty * 4 + i];
                c[i][0] += a * b0;
                c[i][1] += a * b1;
            }
        }
        __syncthreads();
    }
#pragma unroll
    for (int i = 0; i < 4; i++) {
        int m = bm + ty * 4 + i, n = bn + tx * 2;
        if (m < M) {
            if (n < p.N)     p.C[(size_t)m * p.N + n]     = c[i][0];
            if (n + 1 < p.N) p.C[(size_t)m * p.N + n + 1] = c[i][1];
        }
    }
}

// =====================================================================
// GEMM micro-kernel: 64x64 tile, BK=16, 128 threads, 8m x 4n per thread,
// DOUBLE-BUFFERED smem (one __syncthreads per K-step).
// =====================================================================
#define GEMM_DECL()                                                     \
    __shared__ float As[2][16][68];                                     \
    __shared__ float Bs[2][16][68];                                     \
    const int tid = threadIdx.x;                                        \
    const int tx  = tid & 15;       /* 4n  */                           \
    const int ty  = tid >> 4;       /* 8m  */                           \
    const int a_k = (tid & 7) * 2;  /* 0..14 */                         \
    const int a_m = tid >> 3;       /* 0..15 */                         \
    const int b_n = tid & 63;                                           \
    const int b_k = tid >> 6;       /* 0..1 */                          \
    float2 pa[4]; float pb[8];                                          \
    ULL c[4][4];                                                        \
    _Pragma("unroll")                                                   \
    for (int i = 0; i < 4; i++)                                         \
        _Pragma("unroll")                                               \
        for (int j = 0; j < 4; j++) c[i][j] = 0ull;

#define GEMM_STORE(st)                                                  \
    _Pragma("unroll")                                                   \
    for (int i = 0; i < 4; i++) {                                       \
        int m = a_m + i * 16;                                           \
        As[st][a_k][m]     = pa[i].x;                                   \
        As[st][a_k + 1][m] = pa[i].y;                                   \
    }                                                                   \
    _Pragma("unroll")                                                   \
    for (int i = 0; i < 8; i++) Bs[st][b_k + i * 2][b_n] = pb[i];

#define GEMM_MMA(st)                                                    \
    _Pragma("unroll")                                                   \
    for (int kk = 0; kk < 16; kk++) {                                   \
        ulonglong2 a01 = *(const ulonglong2*)&As[st][kk][ty * 8];       \
        ulonglong2 a23 = *(const ulonglong2*)&As[st][kk][ty * 8 + 4];   \
        ULL a[4] = {a01.x, a01.y, a23.x, a23.y};                        \
        float4 bv = *(const float4*)&Bs[st][kk][tx * 4];                \
        ULL b[4] = {pk(bv.x, bv.x), pk(bv.y, bv.y),                     \
                    pk(bv.z, bv.z), pk(bv.w, bv.w)};                    \
        _Pragma("unroll")                                               \
        for (int i = 0; i < 4; i++)                                     \
            _Pragma("unroll")                                           \
            for (int j = 0; j < 4; j++)                                 \
                fma2(c[i][j], a[i], b[j]);                              \
    }

#define GEMM_MAINLOOP(Kv)                                               \
    fetch(0);                                                           \
    GEMM_STORE(0);                                                      \
    __syncthreads();                                                    \
    const int nstep = ((Kv) + 15) >> 4;                                 \
    for (int it = 0; it < nstep; it++) {                                \
        const int cur = it & 1;                                         \
        if (it + 1 < nstep) fetch((it + 1) * 16);                       \
        GEMM_MMA(cur);                                                  \
        if (it + 1 < nstep) { GEMM_STORE(1 - cur); __syncthreads(); }   \
    }

#define GEMM_EPILOGUE(gg, bmv, bnv)                                     \
    _Pragma("unroll")                                                   \
    for (int j = 0; j < 4; j++) {                                       \
        int n = (bnv) + tx * 4 + j;                                     \
        if (n >= (gg).N) continue;                                      \
        float bv = (gg).bias[n];                                        \
        _Pragma("unroll")                                               \
        for (int i = 0; i < 4; i++) {                                   \
            float2 v = upk(c[i][j]);                                    \
            int m = (bmv) + ty * 8 + 2 * i;                             \
            (gg).C[(size_t)m * (gg).ldc + n]       = v.x + bv;          \
            (gg).C[(size_t)(m + 1) * (gg).ldc + n] = v.y + bv;          \
        }                                                               \
    }

// ---------------------------------------------------------------------
// GEMM1: H1 = U @ W1c + b1
// ---------------------------------------------------------------------
__global__ __launch_bounds__(128, 5)
void gemm1_fused(GemmArgs g0, GemmArgs g1)
{
    const GemmArgs g = blockIdx.z ? g1 : g0;
    const int bn = blockIdx.x * 64;
    if (bn >= g.N) return;
    const int bm = blockIdx.y * 64;

    GEMM_DECL();

    auto fetch = [&](int k0) {
        int kg = k0 + a_k;
#pragma unroll
        for (int i = 0; i < 4; i++) {
            int m = bm + a_m + i * 16;
            float2 v = make_float2(0.f, 0.f);
            if (kg + 1 < g.K)  v = *(const float2*)(g.A + (size_t)m * g.K + kg);
            else if (kg < g.K) v.x = g.A[(size_t)m * g.K + kg];
            pa[i] = v;
        }
#pragma unroll
        for (int i = 0; i < 8; i++) {
            int kgb = k0 + b_k + i * 2;
            int ng = bn + b_n;
            pb[i] = (kgb < g.K && ng < g.N) ? g.B[(size_t)kgb * g.N + ng] : 0.f;
        }
    };

    GEMM_MAINLOOP(g.K);
    GEMM_EPILOGUE(g, bm, bn);
}

// ---------------------------------------------------------------------
// GEMM2 with in-block LN stats + fused LN+ReLU on A:
// out = relu((H1 - mu)*rstd*gam + bet) @ W2 + b2
// ---------------------------------------------------------------------
__global__ __launch_bounds__(128, 5)
void gemm2_lnA(GemmArgs g0, GemmArgs g1,
               const float* __restrict__ gm0, const float* __restrict__ bt0,
               const float* __restrict__ gm1, const float* __restrict__ bt1)
{
    const GemmArgs g = blockIdx.z ? g1 : g0;
    const float* gam = blockIdx.z ? gm1 : gm0;
    const float* bet = blockIdx.z ? bt1 : bt0;
    const int bn = blockIdx.x * 64;
    if (bn >= g.N) return;
    const int bm = blockIdx.y * 64;

    __shared__ float muS[64], rsS[64];

    GEMM_DECL();

    // prologue: row stats for this block's 64 rows (4 warps x 16 rows)
    {
        const int w = tid >> 5, lane = tid & 31;
        const float invN = 1.f / (float)g.K;
        for (int r = 0; r < 16; r++) {
            int row = w * 16 + r;
            const float* src = g.A + (size_t)(bm + row) * g.K;
            float s = 0.f, s2 = 0.f;
            for (int j = lane; j < g.K; j += 32) {
                float v = src[j];
                s += v; s2 = fmaf(v, v, s2);
            }
#pragma unroll
            for (int o = 16; o > 0; o >>= 1) {
                s  += __shfl_xor_sync(0xffffffffu, s, o);
                s2 += __shfl_xor_sync(0xffffffffu, s2, o);
            }
            if (lane == 0) {
                float mu = s * invN;
                float var = s2 * invN - mu * mu;
                muS[row] = mu;
                rsS[row] = rsqrtf(var + 1e-5f);
            }
        }
    }
    __syncthreads();

    auto fetch = [&](int k0) {
        int kg = k0 + a_k;
        bool ok0 = (kg < g.K), ok1 = (kg + 1 < g.K);
        float2 gk = make_float2(0.f, 0.f), bb = make_float2(0.f, 0.f);
        if (ok1)      { gk = *(const float2*)(gam + kg); bb = *(const float2*)(bet + kg); }
        else if (ok0) { gk.x = gam[kg]; bb.x = bet[kg]; }
#pragma unroll
        for (int i = 0; i < 4; i++) {
            int mloc = a_m + i * 16;
            int m = bm + mloc;
            float2 v = make_float2(0.f, 0.f);
            if (ok1)      v = *(const float2*)(g.A + (size_t)m * g.K + kg);
            else if (ok0) v.x = g.A[(size_t)m * g.K + kg];
            float mu = muS[mloc], rs = rsS[mloc];
            float2 r = make_float2(0.f, 0.f);
            if (ok0) r.x = fmaxf(0.f, (v.x - mu) * rs * gk.x + bb.x);
            if (ok1) r.y = fmaxf(0.f, (v.y - mu) * rs * gk.y + bb.y);
            pa[i] = r;
        }
#pragma unroll
        for (int i = 0; i < 8; i++) {
            int kgb = k0 + b_k + i * 2;
            int ng = bn + b_n;
            pb[i] = (kgb < g.K && ng < g.N) ? g.B[(size_t)kgb * g.N + ng] : 0.f;
        }
    };

    GEMM_MAINLOOP(g.K);
    GEMM_EPILOGUE(g, bm, bn);
}

// =====================================================================
// Host launcher
// =====================================================================
extern "C" void kernel_launch(void* const* d_in, const int* in_sizes, int n_in,
                              void* d_out, int out_size)
{
    const float* emb_P  = (const float*)d_in[0];
    const float* mask_P = (const float*)d_in[1];
    const float* emb_H  = (const float*)d_in[2];
    const float* mask_H = (const float*)d_in[3];
    const float* pep_Bc = (const float*)d_in[4];
    const float* pep_Ac = (const float*)d_in[5];
    const float* pep_Hc = (const float*)d_in[6];
    const float* pep_W1 = (const float*)d_in[7];
    const float* pep_b1 = (const float*)d_in[8];
    const float* pep_g  = (const float*)d_in[9];
    const float* pep_be = (const float*)d_in[10];
    const float* pep_W2 = (const float*)d_in[11];
    const float* pep_b2 = (const float*)d_in[12];
    const float* hla_Bc = (const float*)d_in[13];
    const float* hla_Ac = (const float*)d_in[14];
    const float* hla_Hc = (const float*)d_in[15];
    const float* hla_W1 = (const float*)d_in[16];
    const float* hla_b1 = (const float*)d_in[17];
    const float* hla_g  = (const float*)d_in[18];
    const float* hla_be = (const float*)d_in[19];
    const float* hla_W2 = (const float*)d_in[20];
    const float* hla_b2 = (const float*)d_in[21];
    float* out = (float*)d_out;

    float *UP, *UH, *W1cP, *W1cH, *H1P, *H1H;
    cudaGetSymbolAddress((void**)&UP,   g_UP);
    cudaGetSymbolAddress((void**)&UH,   g_UH);
    cudaGetSymbolAddress((void**)&W1cP, g_W1cP);
    cudaGetSymbolAddress((void**)&W1cH, g_W1cH);
    cudaGetSymbolAddress((void**)&H1P,  g_H1P);
    cudaGetSymbolAddress((void**)&H1H,  g_H1H);

    // dyn smem: phase1 (L=384): 384*64 + 2*384*8 = 30720 ; phase2 = 24832
    const int smemEnc = 384 * 64 + 2 * 384 * 8;
    cudaFuncSetAttribute(encoders, cudaFuncAttributeMaxDynamicSharedMemorySize, smemEnc);

    // weight precombine (independent, tiny)
    {
        PreArgs pP { pep_Hc, pep_W1, W1cP, 358, 358, 12, 96 };
        PreArgs pH { hla_Hc, hla_W1, W1cH, 154, 154, 5, 40 };
        precombine<<<dim3(96, 1, 2), 128>>>(pP, pH);
    }

    // encoders: both branches, 2 samples/block
    {
        EncArgs eP { emb_P, mask_P, pep_Ac, pep_Bc, UP, 32 };
        EncArgs eH { emb_H, mask_H, hla_Ac, hla_Bc, UH, 384 };
        encoders<<<dim3(2048, 1, 2), 128, smemEnc>>>(eP, eH);
    }

    // GEMM1: H1 = U @ W1c + b1
    {
        GemmArgs gp { UP, W1cP, pep_b1, H1P, 358, 256, 358 };
        GemmArgs gh { UH, W1cH, hla_b1, H1H, 154, 256, 154 };
        gemm1_fused<<<dim3(6, 64, 2), 128>>>(gp, gh);
    }

    // GEMM2 (stats in-block) : out = relu(LN(H1)) @ W2 + b2
    {
        GemmArgs gp { H1P, pep_W2, pep_b2, out,       358, 358, 512 };
        GemmArgs gh { H1H, hla_W2, hla_b2, out + 358, 154, 154, 512 };
        gemm2_lnA<<<dim3(6, 64, 2), 128>>>(gp, gh,
                                           pep_g, pep_be, hla_g, hla_be);
    }
}